// round 1
// baseline (speedup 1.0000x reference)
#include <cuda_runtime.h>
#include <cuda_bf16.h>

// Problem constants
#define N_  8192
#define M_  8192
#define D_  64
#define H_  32
#define T_  8

#define MSPLIT 32              // M-dimension chunks (grid.y)
#define CHUNK  (M_ / MSPLIT)   // 256 Y rows per chunk
#define TJ     128             // Y rows per shared tile
#define BLK    256             // threads per block

// ---------------- scratch (no allocations allowed) ----------------
__device__ float g_Ff[(N_ + M_) * H_];            // MLP features: X rows then Y rows (2 MB)
__device__ float g_Fn[N_ + M_];                   // squared norms
__device__ float g_part[(size_t)N_ * MSPLIT * (T_ + 1)]; // partial (acc[8], accK) per (row, chunk)

// ---------------- kernel 1: MLP features for X and Y ----------------
__global__ __launch_bounds__(256)
void mlp_kernel(const float* __restrict__ X, const float* __restrict__ Y,
                const float* __restrict__ W1, const float* __restrict__ b1,
                const float* __restrict__ W2, const float* __restrict__ b2,
                const float* __restrict__ W3, const float* __restrict__ b3)
{
    __shared__ float sW1[D_ * H_];
    __shared__ float sW2[H_ * H_];
    __shared__ float sW3[H_ * H_];
    __shared__ float sb1[H_], sb2[H_], sb3[H_];

    int tid = threadIdx.x;
    for (int i = tid; i < D_ * H_; i += 256) sW1[i] = W1[i];
    for (int i = tid; i < H_ * H_; i += 256) { sW2[i] = W2[i]; sW3[i] = W3[i]; }
    if (tid < H_) { sb1[tid] = b1[tid]; sb2[tid] = b2[tid]; sb3[tid] = b3[tid]; }
    __syncthreads();

    int r = blockIdx.x * 256 + tid;     // grid covers N_+M_ rows exactly
    const float* src = (r < N_) ? (X + (size_t)r * D_) : (Y + (size_t)(r - N_) * D_);

    float x[D_];
#pragma unroll
    for (int k = 0; k < D_ / 4; k++) {
        float4 v = ((const float4*)src)[k];
        x[4*k+0] = v.x; x[4*k+1] = v.y; x[4*k+2] = v.z; x[4*k+3] = v.w;
    }

    // layer 1: [64]->[32]
    float h1[H_];
#pragma unroll
    for (int j = 0; j < H_; j++) h1[j] = sb1[j];
#pragma unroll
    for (int k = 0; k < D_; k++) {
        float xk = x[k];
#pragma unroll
        for (int j = 0; j < H_; j++) h1[j] += xk * sW1[k * H_ + j];
    }
#pragma unroll
    for (int j = 0; j < H_; j++) h1[j] = fmaxf(h1[j], 0.f);

    // layer 2: [32]->[32]
    float h2[H_];
#pragma unroll
    for (int j = 0; j < H_; j++) h2[j] = sb2[j];
#pragma unroll
    for (int k = 0; k < H_; k++) {
        float hk = h1[k];
#pragma unroll
        for (int j = 0; j < H_; j++) h2[j] += hk * sW2[k * H_ + j];
    }
#pragma unroll
    for (int j = 0; j < H_; j++) h2[j] = fmaxf(h2[j], 0.f);

    // layer 3: [32]->[32]
    float h3[H_];
#pragma unroll
    for (int j = 0; j < H_; j++) h3[j] = sb3[j];
#pragma unroll
    for (int k = 0; k < H_; k++) {
        float hk = h2[k];
#pragma unroll
        for (int j = 0; j < H_; j++) h3[j] += hk * sW3[k * H_ + j];
    }

    float nrm = 0.f;
#pragma unroll
    for (int j = 0; j < H_; j++) {
        float v = fmaxf(h3[j], 0.f);
        g_Ff[(size_t)r * H_ + j] = v;
        nrm += v * v;
    }
    g_Fn[r] = nrm;
}

// ---------------- kernel 2: fused distance/exp/weighted-accumulate ----------------
// grid: (N_/BLK, MSPLIT). Each thread owns one X row; each block.y owns a 256-row
// Y chunk, streamed through shared memory in 128-row tiles.
__global__ __launch_bounds__(BLK)
void dist_kernel(const float* __restrict__ Yt)
{
    __shared__ float sYf[TJ * H_];   // 16 KB
    __shared__ float syn[TJ];        // 512 B
    __shared__ float sYt[TJ * T_];   // 4 KB

    int tid = threadIdx.x;
    int i = blockIdx.x * BLK + tid;
    int m0 = blockIdx.y * CHUNK;

    // my Xf row + norm (resident in registers)
    float xf[H_];
#pragma unroll
    for (int q = 0; q < H_ / 4; q++) {
        float4 v = ((const float4*)(g_Ff + (size_t)i * H_))[q];
        xf[4*q+0] = v.x; xf[4*q+1] = v.y; xf[4*q+2] = v.z; xf[4*q+3] = v.w;
    }
    float xn = g_Fn[i];

    float acc[T_];
#pragma unroll
    for (int t = 0; t < T_; t++) acc[t] = 0.f;
    float accK = 0.f;

#pragma unroll 1
    for (int tile = 0; tile < CHUNK / TJ; tile++) {
        int mb = m0 + tile * TJ;

        // cooperative tile load (float4 everywhere)
        const float4* yf4 = (const float4*)(g_Ff + (size_t)(N_ + mb) * H_);
#pragma unroll
        for (int q = 0; q < (TJ * H_ / 4) / BLK; q++)   // 4 per thread
            ((float4*)sYf)[tid + q * BLK] = yf4[tid + q * BLK];
        if (tid < TJ) syn[tid] = g_Fn[N_ + mb + tid];
        ((float4*)sYt)[tid] = ((const float4*)(Yt + (size_t)mb * T_))[tid]; // 256 float4 = TJ*T_
        __syncthreads();

#pragma unroll 4
        for (int j = 0; j < TJ; j++) {
            const float4* y4 = (const float4*)(sYf + j * H_);
            // 4 independent partial dots for ILP
            float d0 = 0.f, d1 = 0.f, d2 = 0.f, d3 = 0.f;
#pragma unroll
            for (int q = 0; q < H_ / 16; q++) {     // 2 iterations
                float4 a = y4[4*q+0], b = y4[4*q+1], c = y4[4*q+2], d = y4[4*q+3];
                d0 += xf[16*q+ 0]*a.x + xf[16*q+ 1]*a.y + xf[16*q+ 2]*a.z + xf[16*q+ 3]*a.w;
                d1 += xf[16*q+ 4]*b.x + xf[16*q+ 5]*b.y + xf[16*q+ 6]*b.z + xf[16*q+ 7]*b.w;
                d2 += xf[16*q+ 8]*c.x + xf[16*q+ 9]*c.y + xf[16*q+10]*c.z + xf[16*q+11]*c.w;
                d3 += xf[16*q+12]*d.x + xf[16*q+13]*d.y + xf[16*q+14]*d.z + xf[16*q+15]*d.w;
            }
            float dot = (d0 + d1) + (d2 + d3);
            float sq = fmaxf(xn + syn[j] - 2.f * dot, 0.f);
            float kv = __expf(-0.5f * sq);
            accK += kv;
            float4 t0 = ((const float4*)(sYt + j * T_))[0];
            float4 t1 = ((const float4*)(sYt + j * T_))[1];
            acc[0] += kv * t0.x; acc[1] += kv * t0.y; acc[2] += kv * t0.z; acc[3] += kv * t0.w;
            acc[4] += kv * t1.x; acc[5] += kv * t1.y; acc[6] += kv * t1.z; acc[7] += kv * t1.w;
        }
        __syncthreads();
    }

    float* p = g_part + ((size_t)i * MSPLIT + blockIdx.y) * (T_ + 1);
#pragma unroll
    for (int t = 0; t < T_; t++) p[t] = acc[t];
    p[T_] = accK;
}

// ---------------- kernel 3: combine partials, normalize ----------------
__global__ __launch_bounds__(256)
void reduce_kernel(float* __restrict__ out)
{
    int i = blockIdx.x * 256 + threadIdx.x;   // one thread per X row
    const float* p = g_part + (size_t)i * MSPLIT * (T_ + 1);
    float s[T_];
#pragma unroll
    for (int t = 0; t < T_; t++) s[t] = 0.f;
    float sk = 0.f;
#pragma unroll
    for (int c = 0; c < MSPLIT; c++) {
#pragma unroll
        for (int t = 0; t < T_; t++) s[t] += p[c * (T_ + 1) + t];
        sk += p[c * (T_ + 1) + T_];
    }
    float inv = 1.f / sk;
#pragma unroll
    for (int t = 0; t < T_; t++) out[(size_t)i * T_ + t] = s[t] * inv;
}

// ---------------- launch ----------------
extern "C" void kernel_launch(void* const* d_in, const int* in_sizes, int n_in,
                              void* d_out, int out_size)
{
    (void)in_sizes; (void)n_in; (void)out_size;
    const float* X  = (const float*)d_in[0];
    const float* Y  = (const float*)d_in[1];
    const float* Yt = (const float*)d_in[2];
    const float* W1 = (const float*)d_in[3];
    const float* b1 = (const float*)d_in[4];
    const float* W2 = (const float*)d_in[5];
    const float* b2 = (const float*)d_in[6];
    const float* W3 = (const float*)d_in[7];
    const float* b3 = (const float*)d_in[8];
    float* out = (float*)d_out;

    mlp_kernel<<<(N_ + M_) / 256, 256>>>(X, Y, W1, b1, W2, b2, W3, b3);
    dist_kernel<<<dim3(N_ / BLK, MSPLIT), BLK>>>(Yt);
    reduce_kernel<<<N_ / 256, 256>>>(out);
}

// round 2
// speedup vs baseline: 1.3360x; 1.3360x over previous
#include <cuda_runtime.h>
#include <cuda_bf16.h>

// Problem constants
#define N_  8192
#define M_  8192
#define D_  64
#define H_  32
#define T_  8

#define MSPLIT 32              // M-dimension chunks (grid.y)
#define CHUNK  (M_ / MSPLIT)   // 256 Y rows per chunk
#define TJ     128             // Y rows per shared tile
#define BLK    128             // threads per block (dist)
#define RX     2               // X rows per thread

#define LOG2E      1.4426950408889634f
#define NEG_H_L2E  0.7213475204444817f   // 0.5*log2(e); stored negated

typedef unsigned long long u64;

// ---------------- scratch (no allocations allowed) ----------------
__device__ float g_Ff[(N_ + M_) * H_];            // MLP features (X rows then Y rows)
__device__ float g_Fn[N_ + M_];                   // -0.5*log2e*||f||^2 per row
__device__ float g_part[(size_t)N_ * MSPLIT * (T_ + 1)];

// ---------------- f32x2 helpers ----------------
__device__ __forceinline__ u64 fma2(u64 a, u64 b, u64 c) {
    u64 d; asm("fma.rn.f32x2 %0, %1, %2, %3;" : "=l"(d) : "l"(a), "l"(b), "l"(c)); return d;
}
__device__ __forceinline__ u64 add2(u64 a, u64 b) {
    u64 d; asm("add.rn.f32x2 %0, %1, %2;" : "=l"(d) : "l"(a), "l"(b)); return d;
}
__device__ __forceinline__ u64 mul2(u64 a, u64 b) {
    u64 d; asm("mul.rn.f32x2 %0, %1, %2;" : "=l"(d) : "l"(a), "l"(b)); return d;
}
__device__ __forceinline__ u64 pack2(float lo, float hi) {
    u64 d; asm("mov.b64 %0, {%1, %2};" : "=l"(d) : "f"(lo), "f"(hi)); return d;
}
__device__ __forceinline__ void unpack2(u64 v, float& lo, float& hi) {
    asm("mov.b64 {%0, %1}, %2;" : "=f"(lo), "=f"(hi) : "l"(v));
}
__device__ __forceinline__ float ex2(float x) {
    float r; asm("ex2.approx.ftz.f32 %0, %1;" : "=f"(r) : "f"(x)); return r;
}

// ---------------- kernel 1: MLP features for X and Y ----------------
__global__ __launch_bounds__(128)
void mlp_kernel(const float* __restrict__ X, const float* __restrict__ Y,
                const float* __restrict__ W1, const float* __restrict__ b1,
                const float* __restrict__ W2, const float* __restrict__ b2,
                const float* __restrict__ W3, const float* __restrict__ b3)
{
    __shared__ float sW1[D_ * H_];
    __shared__ float sW2[H_ * H_];
    __shared__ float sW3[H_ * H_];
    __shared__ float sb1[H_], sb2[H_], sb3[H_];

    int tid = threadIdx.x;
    for (int i = tid; i < D_ * H_; i += 128) sW1[i] = W1[i];
    for (int i = tid; i < H_ * H_; i += 128) { sW2[i] = W2[i]; sW3[i] = W3[i]; }
    if (tid < H_) { sb1[tid] = b1[tid]; sb2[tid] = b2[tid]; sb3[tid] = b3[tid]; }
    __syncthreads();

    int r = blockIdx.x * 128 + tid;     // grid covers N_+M_ rows exactly
    const float* src = (r < N_) ? (X + (size_t)r * D_) : (Y + (size_t)(r - N_) * D_);

    float x[D_];
#pragma unroll
    for (int k = 0; k < D_ / 4; k++) {
        float4 v = ((const float4*)src)[k];
        x[4*k+0] = v.x; x[4*k+1] = v.y; x[4*k+2] = v.z; x[4*k+3] = v.w;
    }

    float h1[H_];
#pragma unroll
    for (int j = 0; j < H_; j++) h1[j] = sb1[j];
#pragma unroll
    for (int k = 0; k < D_; k++) {
        float xk = x[k];
#pragma unroll
        for (int j = 0; j < H_; j++) h1[j] += xk * sW1[k * H_ + j];
    }
#pragma unroll
    for (int j = 0; j < H_; j++) h1[j] = fmaxf(h1[j], 0.f);

    float h2[H_];
#pragma unroll
    for (int j = 0; j < H_; j++) h2[j] = sb2[j];
#pragma unroll
    for (int k = 0; k < H_; k++) {
        float hk = h1[k];
#pragma unroll
        for (int j = 0; j < H_; j++) h2[j] += hk * sW2[k * H_ + j];
    }
#pragma unroll
    for (int j = 0; j < H_; j++) h2[j] = fmaxf(h2[j], 0.f);

    float h3[H_];
#pragma unroll
    for (int j = 0; j < H_; j++) h3[j] = sb3[j];
#pragma unroll
    for (int k = 0; k < H_; k++) {
        float hk = h2[k];
#pragma unroll
        for (int j = 0; j < H_; j++) h3[j] += hk * sW3[k * H_ + j];
    }

    float nrm = 0.f;
#pragma unroll
    for (int j = 0; j < H_; j++) {
        float v = fmaxf(h3[j], 0.f);
        g_Ff[(size_t)r * H_ + j] = v;
        nrm += v * v;
    }
    g_Fn[r] = -NEG_H_L2E * nrm;          // -0.5*log2e*||f||^2
}

// ---------------- kernel 2: fused distance/exp/weighted-accumulate ----------------
// grid: (N_/(BLK*RX), MSPLIT). Each thread owns RX=2 X rows; each block.y owns a
// 256-row Y chunk, streamed through shared memory in 128-row tiles.
// exp(-0.5*sq) = ex2( min( log2e*dot + cx + cy, 0 ) ) with xf pre-scaled by log2e.
__global__ __launch_bounds__(BLK)
void dist_kernel(const float* __restrict__ Yt)
{
    __shared__ float sYf[TJ * H_];   // 16 KB
    __shared__ float sc[TJ];         // cy = -0.5*log2e*||yf||^2
    __shared__ float sYt[TJ * T_];   // 4 KB

    int tid = threadIdx.x;
    int i0 = blockIdx.x * (BLK * RX) + tid;
    int i1 = i0 + BLK;
    int m0 = blockIdx.y * CHUNK;

    // X feature rows, pre-scaled by log2(e), packed as f32x2
    u64 px0[H_ / 2], px1[H_ / 2];
    {
        const u64 l2e2 = pack2(LOG2E, LOG2E);
        const u64* a = (const u64*)(g_Ff + (size_t)i0 * H_);
        const u64* b = (const u64*)(g_Ff + (size_t)i1 * H_);
#pragma unroll
        for (int p = 0; p < H_ / 2; p++) { px0[p] = mul2(a[p], l2e2); px1[p] = mul2(b[p], l2e2); }
    }
    float cx0 = g_Fn[i0];
    float cx1 = g_Fn[i1];

    u64 acc0[T_ / 2], acc1[T_ / 2];
#pragma unroll
    for (int q = 0; q < T_ / 2; q++) { acc0[q] = 0ull; acc1[q] = 0ull; }
    float accK0 = 0.f, accK1 = 0.f;

#pragma unroll 1
    for (int tile = 0; tile < CHUNK / TJ; tile++) {
        int mb = m0 + tile * TJ;

        const float4* yf4 = (const float4*)(g_Ff + (size_t)(N_ + mb) * H_);
#pragma unroll
        for (int q = 0; q < (TJ * H_ / 4) / BLK; q++)     // 8 per thread
            ((float4*)sYf)[tid + q * BLK] = yf4[tid + q * BLK];
        sc[tid] = g_Fn[N_ + mb + tid];                    // TJ == BLK
#pragma unroll
        for (int q = 0; q < (TJ * T_ / 4) / BLK; q++)     // 2 per thread
            ((float4*)sYt)[tid + q * BLK] = ((const float4*)(Yt + (size_t)mb * T_))[tid + q * BLK];
        __syncthreads();

#pragma unroll 2
        for (int j = 0; j < TJ; j++) {
            const u64* y = (const u64*)(sYf + j * H_);    // 16 u64 (LDS.128-pairs)
            u64 d0a = 0ull, d0b = 0ull, d1a = 0ull, d1b = 0ull;
#pragma unroll
            for (int p = 0; p < H_ / 4; p++) {            // 8 iters, 2 pairs each
                u64 ya = y[2*p], yb = y[2*p+1];
                d0a = fma2(px0[2*p],   ya, d0a);
                d0b = fma2(px0[2*p+1], yb, d0b);
                d1a = fma2(px1[2*p],   ya, d1a);
                d1b = fma2(px1[2*p+1], yb, d1b);
            }
            float lo, hi, dot0, dot1;
            unpack2(add2(d0a, d0b), lo, hi); dot0 = lo + hi;
            unpack2(add2(d1a, d1b), lo, hi); dot1 = lo + hi;

            float cy = sc[j];
            float kv0 = ex2(fminf(dot0 + cx0 + cy, 0.f));
            float kv1 = ex2(fminf(dot1 + cx1 + cy, 0.f));
            accK0 += kv0; accK1 += kv1;

            const u64* t = (const u64*)(sYt + j * T_);    // 4 u64
            u64 kk0 = pack2(kv0, kv0), kk1 = pack2(kv1, kv1);
#pragma unroll
            for (int q = 0; q < T_ / 2; q++) {
                u64 tv = t[q];
                acc0[q] = fma2(kk0, tv, acc0[q]);
                acc1[q] = fma2(kk1, tv, acc1[q]);
            }
        }
        __syncthreads();
    }

    float* p0 = g_part + ((size_t)i0 * MSPLIT + blockIdx.y) * (T_ + 1);
    float* p1 = g_part + ((size_t)i1 * MSPLIT + blockIdx.y) * (T_ + 1);
#pragma unroll
    for (int q = 0; q < T_ / 2; q++) {
        float lo, hi;
        unpack2(acc0[q], lo, hi); p0[2*q] = lo; p0[2*q+1] = hi;
        unpack2(acc1[q], lo, hi); p1[2*q] = lo; p1[2*q+1] = hi;
    }
    p0[T_] = accK0;
    p1[T_] = accK1;
}

// ---------------- kernel 3: combine partials, normalize ----------------
__global__ __launch_bounds__(256)
void reduce_kernel(float* __restrict__ out)
{
    int i = blockIdx.x * 256 + threadIdx.x;   // one thread per X row
    const float* p = g_part + (size_t)i * MSPLIT * (T_ + 1);
    float s[T_];
#pragma unroll
    for (int t = 0; t < T_; t++) s[t] = 0.f;
    float sk = 0.f;
#pragma unroll
    for (int c = 0; c < MSPLIT; c++) {
#pragma unroll
        for (int t = 0; t < T_; t++) s[t] += p[c * (T_ + 1) + t];
        sk += p[c * (T_ + 1) + T_];
    }
    float inv = 1.f / sk;
#pragma unroll
    for (int t = 0; t < T_; t++) out[(size_t)i * T_ + t] = s[t] * inv;
}

// ---------------- launch ----------------
extern "C" void kernel_launch(void* const* d_in, const int* in_sizes, int n_in,
                              void* d_out, int out_size)
{
    (void)in_sizes; (void)n_in; (void)out_size;
    const float* X  = (const float*)d_in[0];
    const float* Y  = (const float*)d_in[1];
    const float* Yt = (const float*)d_in[2];
    const float* W1 = (const float*)d_in[3];
    const float* b1 = (const float*)d_in[4];
    const float* W2 = (const float*)d_in[5];
    const float* b2 = (const float*)d_in[6];
    const float* W3 = (const float*)d_in[7];
    const float* b3 = (const float*)d_in[8];
    float* out = (float*)d_out;

    mlp_kernel<<<(N_ + M_) / 128, 128>>>(X, Y, W1, b1, W2, b2, W3, b3);
    dist_kernel<<<dim3(N_ / (BLK * RX), MSPLIT), BLK>>>(Yt);
    reduce_kernel<<<N_ / 256, 256>>>(out);
}

// round 5
// speedup vs baseline: 2.5296x; 1.8934x over previous
#include <cuda_runtime.h>
#include <cuda_fp16.h>
#include <cstdint>

// Problem constants
#define N_  8192
#define M_  8192
#define D_  64
#define H_  32
#define T_  8

#define MSPLIT 2
#define TT     128                    // tile size (M rows per CTA, N cols per iter)
#define TILES  ((M_ / MSPLIT) / TT)   // 32 tiles per CTA
#define LOG2E     1.4426950408889634f
#define HALF_L2E  0.7213475204444817f

typedef unsigned long long u64;
typedef unsigned int u32;

// ---------------- global scratch ----------------
// X rows (0..N-1): features pre-scaled by log2(e). Y rows (N..N+M-1): unscaled.
__device__ __half g_Fhi[(N_ + M_) * H_];
__device__ __half g_Flo[(N_ + M_) * H_];
__device__ float  g_Fn[N_ + M_];           // -0.5*log2e*||f||^2 (unscaled f)
__device__ __half g_Vhi[M_ * T_];          // Yt hi, [j][t]
__device__ __half g_Vlo[M_ * T_];          // Yt lo residual
__device__ float  g_part[(size_t)N_ * MSPLIT * (T_ + 1)];

// ---------------- helpers ----------------
__device__ __forceinline__ u32 smem_u32(const void* p) {
    u32 a; asm("{ .reg .u64 t; cvta.to.shared.u64 t, %1; cvt.u32.u64 %0, t; }" : "=r"(a) : "l"(p));
    return a;
}
__device__ __forceinline__ float ex2f(float x) {
    float r; asm("ex2.approx.ftz.f32 %0, %1;" : "=f"(r) : "f"(x)); return r;
}
__device__ __forceinline__ void ldmx4(u32& r0, u32& r1, u32& r2, u32& r3, u32 addr) {
    asm volatile("ldmatrix.sync.aligned.m8n8.x4.shared.b16 {%0,%1,%2,%3}, [%4];"
        : "=r"(r0), "=r"(r1), "=r"(r2), "=r"(r3) : "r"(addr));
}
__device__ __forceinline__ void ldmx2t(u32& r0, u32& r1, u32 addr) {
    asm volatile("ldmatrix.sync.aligned.m8n8.x2.trans.shared.b16 {%0,%1}, [%2];"
        : "=r"(r0), "=r"(r1) : "r"(addr));
}
__device__ __forceinline__ void mma16816(float& c0, float& c1, float& c2, float& c3,
                                         u32 a0, u32 a1, u32 a2, u32 a3, u32 b0, u32 b1) {
    asm volatile("mma.sync.aligned.m16n8k16.row.col.f32.f16.f16.f32 "
        "{%0,%1,%2,%3},{%4,%5,%6,%7},{%8,%9},{%0,%1,%2,%3};"
        : "+f"(c0), "+f"(c1), "+f"(c2), "+f"(c3)
        : "r"(a0), "r"(a1), "r"(a2), "r"(a3), "r"(b0), "r"(b1));
}

// ---------------- SMEM layout (byte offsets into dynamic smem) ----------------
// feature tiles use 80-byte row pitch (64B data) -> conflict-free ldmatrix
#define PITCH   80
#define S_AHI   0                       // 128 rows * 80B
#define S_ALO   10240
#define S_B     20480                   // [buf][hi/lo] 4 x 10240
#define S_V     61440                   // [buf][hi/lo] 4 x 2048 (V rows: 16B, j*16)
#define S_CY    69632                   // 2 x 128 floats
#define SMEM_TOTAL 70656

// ---------------- kernel 1: MLP, warp-per-row ----------------
__global__ __launch_bounds__(256)
void mlp_kernel(const float* __restrict__ X, const float* __restrict__ Y,
                const float* __restrict__ W1, const float* __restrict__ b1,
                const float* __restrict__ W2, const float* __restrict__ b2,
                const float* __restrict__ W3, const float* __restrict__ b3)
{
    __shared__ float sW1[D_ * H_], sW2[H_ * H_], sW3[H_ * H_];
    __shared__ float sb1[H_], sb2[H_], sb3[H_];
    int tid = threadIdx.x, w = tid >> 5, l = tid & 31;
    for (int i = tid; i < D_ * H_; i += 256) sW1[i] = W1[i];
    for (int i = tid; i < H_ * H_; i += 256) { sW2[i] = W2[i]; sW3[i] = W3[i]; }
    if (tid < H_) { sb1[tid] = b1[tid]; sb2[tid] = b2[tid]; sb3[tid] = b3[tid]; }
    __syncthreads();

    int row = blockIdx.x * 8 + w;   // grid covers N_+M_ rows
    const float* src = (row < N_) ? (X + (size_t)row * D_) : (Y + (size_t)(row - N_) * D_);
    float x0 = src[l], x1 = src[32 + l];

    float h = sb1[l];
#pragma unroll
    for (int k = 0; k < 32; k++) h = fmaf(__shfl_sync(0xffffffffu, x0, k), sW1[k * 32 + l], h);
#pragma unroll
    for (int k = 0; k < 32; k++) h = fmaf(__shfl_sync(0xffffffffu, x1, k), sW1[(32 + k) * 32 + l], h);
    h = fmaxf(h, 0.f);

    float h2 = sb2[l];
#pragma unroll
    for (int k = 0; k < 32; k++) h2 = fmaf(__shfl_sync(0xffffffffu, h, k), sW2[k * 32 + l], h2);
    h2 = fmaxf(h2, 0.f);

    float h3 = sb3[l];
#pragma unroll
    for (int k = 0; k < 32; k++) h3 = fmaf(__shfl_sync(0xffffffffu, h2, k), sW3[k * 32 + l], h3);
    float v = fmaxf(h3, 0.f);

    float nx = v * v;
#pragma unroll
    for (int o = 16; o > 0; o >>= 1) nx += __shfl_xor_sync(0xffffffffu, nx, o);

    float vs = (row < N_) ? v * LOG2E : v;     // fold log2e into X side only
    __half hi = __float2half_rn(vs);
    __half lo = __float2half_rn(vs - __half2float(hi));
    g_Fhi[(size_t)row * H_ + l] = hi;
    g_Flo[(size_t)row * H_ + l] = lo;
    if (l == 0) g_Fn[row] = -HALF_L2E * nx;
}

// ---------------- kernel 1b: V = Yt hi/lo, [j][t] ----------------
__global__ __launch_bounds__(256)
void prep_v(const float* __restrict__ Yt)
{
    int idx = blockIdx.x * 256 + threadIdx.x;   // M_*T_
    float v = Yt[idx];
    __half hi = __float2half_rn(v);
    __half lo = __float2half_rn(v - __half2float(hi));
    g_Vhi[idx] = hi;
    g_Vlo[idx] = lo;
}

// ---------------- kernel 2: HMMA flash kernel ----------------
__global__ __launch_bounds__(256)
void dist_kernel()
{
    extern __shared__ char smem[];
    u32 sb = smem_u32(smem);
    int tid = threadIdx.x, w = tid >> 5, l = tid & 31;
    int g = l >> 2, tig = l & 3;
    int row0 = blockIdx.x * TT;
    int m0   = blockIdx.y * (M_ / MSPLIT);

    // ---- preamble: A tile + tile0 of B/V/cy
    {
#pragma unroll
        for (int q = 0; q < 2; q++) {
            int id = tid + q * 256, r = id >> 2, c = id & 3;
            *(uint4*)(smem + S_AHI + r * PITCH + c * 16) = *(const uint4*)(g_Fhi + (size_t)(row0 + r) * H_ + c * 8);
            *(uint4*)(smem + S_ALO + r * PITCH + c * 16) = *(const uint4*)(g_Flo + (size_t)(row0 + r) * H_ + c * 8);
            *(uint4*)(smem + S_B + 0 + r * PITCH + c * 16)     = *(const uint4*)(g_Fhi + (size_t)(N_ + m0 + r) * H_ + c * 8);
            *(uint4*)(smem + S_B + 10240 + r * PITCH + c * 16) = *(const uint4*)(g_Flo + (size_t)(N_ + m0 + r) * H_ + c * 8);
        }
        if (tid < 128) {
            *(uint4*)(smem + S_V + tid * 16) = *(const uint4*)(g_Vhi + (size_t)(m0 + tid) * T_);
            ((float*)(smem + S_CY))[tid] = g_Fn[N_ + m0 + tid];
        } else {
            int t2 = tid - 128;
            *(uint4*)(smem + S_V + 2048 + t2 * 16) = *(const uint4*)(g_Vlo + (size_t)(m0 + t2) * T_);
        }
    }
    __syncthreads();

    // ---- A fragments (persistent): [kstep][4] hi and lo
    u32 aH0[4], aH1[4], aL0[4], aL1[4];
    {
        u32 arow = (u32)(w * 16 + (l & 15)) * PITCH + (u32)(l >> 4) * 16;
        ldmx4(aH0[0], aH0[1], aH0[2], aH0[3], sb + S_AHI + arow);
        ldmx4(aH1[0], aH1[1], aH1[2], aH1[3], sb + S_AHI + arow + 32);
        ldmx4(aL0[0], aL0[1], aL0[2], aL0[3], sb + S_ALO + arow);
        ldmx4(aL1[0], aL1[1], aL1[2], aL1[3], sb + S_ALO + arow + 32);
    }

    float cx0 = g_Fn[row0 + w * 16 + g];
    float cx1 = g_Fn[row0 + w * 16 + g + 8];

    float o0 = 0.f, o1 = 0.f, o2 = 0.f, o3 = 0.f;   // O accum [2 rows][2 t-cols]
    float s0 = 0.f, s1 = 0.f;                       // kv rowsums

    // precomputed ldmatrix address offsets
    u32 bArow = (u32)((l & 7)) * PITCH + (u32)(l >> 3) * 16;   // + nc*8*PITCH
    u32 vArow = (u32)(l & 15) * 16;                            // + s*16*16

#pragma unroll 1
    for (int i = 0; i < TILES; i++) {
        // prefetch next tile into regs
        uint4 nbh[2], nbl[2], nv; float ncy = 0.f;
        bool pf = (i + 1 < TILES);
        if (pf) {
            int mb = m0 + (i + 1) * TT;
#pragma unroll
            for (int q = 0; q < 2; q++) {
                int id = tid + q * 256, r = id >> 2, c = id & 3;
                nbh[q] = *(const uint4*)(g_Fhi + (size_t)(N_ + mb + r) * H_ + c * 8);
                nbl[q] = *(const uint4*)(g_Flo + (size_t)(N_ + mb + r) * H_ + c * 8);
            }
            if (tid < 128) { nv = *(const uint4*)(g_Vhi + (size_t)(mb + tid) * T_); ncy = g_Fn[N_ + mb + tid]; }
            else           { nv = *(const uint4*)(g_Vlo + (size_t)(mb + tid - 128) * T_); }
        }

        int ib = i & 1;
        u32 Bhi = sb + S_B + ib * 20480, Blo = Bhi + 10240;
        u32 Vhi = sb + S_V + ib * 4096,  Vlo = Vhi + 2048;
        const float* cyb = (const float*)(smem + S_CY + ib * 512);

#pragma unroll 1
        for (int s = 0; s < 8; s++) {
            u32 aP[4], aPl[4];   // P fragments for MMA2 (hi, lo)
#pragma unroll
            for (int hhalf = 0; hhalf < 2; hhalf++) {
                int nc = 2 * s + hhalf;
                u32 bh[4], bl[4];
                ldmx4(bh[0], bh[1], bh[2], bh[3], Bhi + (u32)nc * (8 * PITCH) + bArow);
                ldmx4(bl[0], bl[1], bl[2], bl[3], Blo + (u32)nc * (8 * PITCH) + bArow);

                float c0 = 0.f, c1 = 0.f, c2 = 0.f, c3 = 0.f;
                mma16816(c0, c1, c2, c3, aH0[0], aH0[1], aH0[2], aH0[3], bh[0], bh[1]);
                mma16816(c0, c1, c2, c3, aH1[0], aH1[1], aH1[2], aH1[3], bh[2], bh[3]);
                mma16816(c0, c1, c2, c3, aH0[0], aH0[1], aH0[2], aH0[3], bl[0], bl[1]);
                mma16816(c0, c1, c2, c3, aH1[0], aH1[1], aH1[2], aH1[3], bl[2], bl[3]);
                mma16816(c0, c1, c2, c3, aL0[0], aL0[1], aL0[2], aL0[3], bh[0], bh[1]);
                mma16816(c0, c1, c2, c3, aL1[0], aL1[1], aL1[2], aL1[3], bh[2], bh[3]);

                // epilogue: kv = ex2(min(S + cx + cy, 0))
                float2 cy = *(const float2*)(cyb + nc * 8 + 2 * tig);
                float k0 = ex2f(fminf(c0 + (cx0 + cy.x), 0.f));
                float k1 = ex2f(fminf(c1 + (cx0 + cy.y), 0.f));
                float k2 = ex2f(fminf(c2 + (cx1 + cy.x), 0.f));
                float k3 = ex2f(fminf(c3 + (cx1 + cy.y), 0.f));
                s0 += k0 + k1;
                s1 += k2 + k3;

                __half2 h01 = __floats2half2_rn(k0, k1);
                __half2 h23 = __floats2half2_rn(k2, k3);
                float2 f01 = __half22float2(h01);
                float2 f23 = __half22float2(h23);
                __half2 l01 = __floats2half2_rn(k0 - f01.x, k1 - f01.y);
                __half2 l23 = __floats2half2_rn(k2 - f23.x, k3 - f23.y);
                aP [2 * hhalf]     = *(u32*)&h01;
                aP [2 * hhalf + 1] = *(u32*)&h23;
                aPl[2 * hhalf]     = *(u32*)&l01;
                aPl[2 * hhalf + 1] = *(u32*)&l23;
            }

            // MMA2: O += P @ V  (k = 16 j's of this s)
            u32 vh[2], vl[2];
            ldmx2t(vh[0], vh[1], Vhi + (u32)s * 256 + vArow);
            ldmx2t(vl[0], vl[1], Vlo + (u32)s * 256 + vArow);
            mma16816(o0, o1, o2, o3, aP[0],  aP[1],  aP[2],  aP[3],  vh[0], vh[1]);
            mma16816(o0, o1, o2, o3, aPl[0], aPl[1], aPl[2], aPl[3], vh[0], vh[1]);
            mma16816(o0, o1, o2, o3, aP[0],  aP[1],  aP[2],  aP[3],  vl[0], vl[1]);
        }

        // store prefetched tile into the other buffer
        if (pf) {
            int ib2 = (i + 1) & 1;
            u32 nBhi = sb + S_B + ib2 * 20480, nBlo = nBhi + 10240;
#pragma unroll
            for (int q = 0; q < 2; q++) {
                int id = tid + q * 256, r = id >> 2, c = id & 3;
                *(uint4*)(smem + (nBhi - sb) + r * PITCH + c * 16) = nbh[q];
                *(uint4*)(smem + (nBlo - sb) + r * PITCH + c * 16) = nbl[q];
            }
            if (tid < 128) {
                *(uint4*)(smem + S_V + ib2 * 4096 + tid * 16) = nv;
                ((float*)(smem + S_CY + ib2 * 512))[tid] = ncy;
            } else {
                *(uint4*)(smem + S_V + ib2 * 4096 + 2048 + (tid - 128) * 16) = nv;
            }
        }
        __syncthreads();
    }

    // rowsum reduce within quad (lanes sharing row g)
    s0 += __shfl_xor_sync(0xffffffffu, s0, 1);
    s0 += __shfl_xor_sync(0xffffffffu, s0, 2);
    s1 += __shfl_xor_sync(0xffffffffu, s1, 1);
    s1 += __shfl_xor_sync(0xffffffffu, s1, 2);

    int ra = row0 + w * 16 + g;
    float* pa = g_part + ((size_t)ra * MSPLIT + blockIdx.y) * (T_ + 1);
    float* pb = g_part + ((size_t)(ra + 8) * MSPLIT + blockIdx.y) * (T_ + 1);
    pa[2 * tig] = o0; pa[2 * tig + 1] = o1;
    pb[2 * tig] = o2; pb[2 * tig + 1] = o3;
    if (tig == 0) { pa[T_] = s0; pb[T_] = s1; }
}

// ---------------- kernel 3: combine partials, normalize ----------------
__global__ __launch_bounds__(256)
void reduce_kernel(float* __restrict__ out)
{
    int i = blockIdx.x * 256 + threadIdx.x;
    const float* p = g_part + (size_t)i * MSPLIT * (T_ + 1);
    float s[T_];
#pragma unroll
    for (int t = 0; t < T_; t++) s[t] = 0.f;
    float sk = 0.f;
#pragma unroll
    for (int c = 0; c < MSPLIT; c++) {
#pragma unroll
        for (int t = 0; t < T_; t++) s[t] += p[c * (T_ + 1) + t];
        sk += p[c * (T_ + 1) + T_];
    }
    float inv = 1.f / sk;
#pragma unroll
    for (int t = 0; t < T_; t++) out[(size_t)i * T_ + t] = s[t] * inv;
}

// ---------------- launch ----------------
extern "C" void kernel_launch(void* const* d_in, const int* in_sizes, int n_in,
                              void* d_out, int out_size)
{
    (void)in_sizes; (void)n_in; (void)out_size;
    const float* X  = (const float*)d_in[0];
    const float* Y  = (const float*)d_in[1];
    const float* Yt = (const float*)d_in[2];
    const float* W1 = (const float*)d_in[3];
    const float* b1 = (const float*)d_in[4];
    const float* W2 = (const float*)d_in[5];
    const float* b2 = (const float*)d_in[6];
    const float* W3 = (const float*)d_in[7];
    const float* b3 = (const float*)d_in[8];
    float* out = (float*)d_out;

    cudaFuncSetAttribute(dist_kernel, cudaFuncAttributeMaxDynamicSharedMemorySize, SMEM_TOTAL);

    mlp_kernel<<<(N_ + M_) / 8, 256>>>(X, Y, W1, b1, W2, b2, W3, b3);
    prep_v<<<(M_ * T_) / 256, 256>>>(Yt);
    dist_kernel<<<dim3(N_ / TT, MSPLIT), 256, SMEM_TOTAL>>>();
    reduce_kernel<<<N_ / 256, 256>>>(out);
}

// round 6
// speedup vs baseline: 3.2030x; 1.2662x over previous
#include <cuda_runtime.h>
#include <cuda_fp16.h>
#include <cstdint>

// Problem constants
#define N_  8192
#define M_  8192
#define D_  64
#define H_  32
#define T_  8

#define MSPLIT 4
#define TTM    256                      // X rows per CTA
#define TTN    128                      // Y rows per tile iter
#define TILES  ((M_ / MSPLIT) / TTN)    // 16
#define THREADS 512
#define LOG2E     1.4426950408889634f
#define HALF_L2E  0.7213475204444817f

typedef unsigned long long u64;
typedef unsigned int u32;

// ---------------- global scratch ----------------
__device__ __half g_Fhi[(N_ + M_) * H_];   // X rows pre-scaled by log2e; Y rows raw
__device__ __half g_Flo[(N_ + M_) * H_];
__device__ float  g_Fn[N_ + M_];           // -0.5*log2e*||f||^2
__device__ __half g_Vhi[M_ * T_];          // Yt hi, [j][t]
__device__ __half g_Vlo[M_ * T_];
__device__ float  g_part[(size_t)N_ * MSPLIT * (T_ + 1)];

// ---------------- helpers ----------------
__device__ __forceinline__ u32 smem_u32(const void* p) {
    u32 a; asm("{ .reg .u64 t; cvta.to.shared.u64 t, %1; cvt.u32.u64 %0, t; }" : "=r"(a) : "l"(p));
    return a;
}
__device__ __forceinline__ float ex2f(float x) {
    float r; asm("ex2.approx.ftz.f32 %0, %1;" : "=f"(r) : "f"(x)); return r;
}
__device__ __forceinline__ void ldmx4(u32& r0, u32& r1, u32& r2, u32& r3, u32 addr) {
    asm volatile("ldmatrix.sync.aligned.m8n8.x4.shared.b16 {%0,%1,%2,%3}, [%4];"
        : "=r"(r0), "=r"(r1), "=r"(r2), "=r"(r3) : "r"(addr));
}
__device__ __forceinline__ void ldmx2t(u32& r0, u32& r1, u32 addr) {
    asm volatile("ldmatrix.sync.aligned.m8n8.x2.trans.shared.b16 {%0,%1}, [%2];"
        : "=r"(r0), "=r"(r1) : "r"(addr));
}
__device__ __forceinline__ void mma16816(float& c0, float& c1, float& c2, float& c3,
                                         u32 a0, u32 a1, u32 a2, u32 a3, u32 b0, u32 b1) {
    asm volatile("mma.sync.aligned.m16n8k16.row.col.f32.f16.f16.f32 "
        "{%0,%1,%2,%3},{%4,%5,%6,%7},{%8,%9},{%0,%1,%2,%3};"
        : "+f"(c0), "+f"(c1), "+f"(c2), "+f"(c3)
        : "r"(a0), "r"(a1), "r"(a2), "r"(a3), "r"(b0), "r"(b1));
}

// ---------------- SMEM layout ----------------
#define PITCH   80                      // 64B data + 16B pad -> conflict-free ldmatrix
#define S_AHI   0                       // 256 rows * 80B
#define S_ALO   20480
#define S_B     40960                   // [stage][hi/lo]: stage*20480, lo +10240
#define S_V     81920                   // [stage][hi/lo]: stage*4096, lo +2048
#define S_CY    90112                   // [stage] 512B
#define SMEM_TOTAL 91136

// ---------------- kernel 1: MLP (warp-per-row) + fused V prep ----------------
__global__ __launch_bounds__(256)
void mlp_kernel(const float* __restrict__ X, const float* __restrict__ Y,
                const float* __restrict__ Yt,
                const float* __restrict__ W1, const float* __restrict__ b1,
                const float* __restrict__ W2, const float* __restrict__ b2,
                const float* __restrict__ W3, const float* __restrict__ b3)
{
    if (blockIdx.x >= (N_ + M_) / 8) {      // tail blocks: build V hi/lo
        int idx = (blockIdx.x - (N_ + M_) / 8) * 256 + threadIdx.x;  // M_*T_
        float v = Yt[idx];
        __half hi = __float2half_rn(v);
        g_Vhi[idx] = hi;
        g_Vlo[idx] = __float2half_rn(v - __half2float(hi));
        return;
    }

    __shared__ float sW1[D_ * H_], sW2[H_ * H_], sW3[H_ * H_];
    __shared__ float sb1[H_], sb2[H_], sb3[H_];
    int tid = threadIdx.x, w = tid >> 5, l = tid & 31;
    for (int i = tid; i < D_ * H_; i += 256) sW1[i] = W1[i];
    for (int i = tid; i < H_ * H_; i += 256) { sW2[i] = W2[i]; sW3[i] = W3[i]; }
    if (tid < H_) { sb1[tid] = b1[tid]; sb2[tid] = b2[tid]; sb3[tid] = b3[tid]; }
    __syncthreads();

    int row = blockIdx.x * 8 + w;
    const float* src = (row < N_) ? (X + (size_t)row * D_) : (Y + (size_t)(row - N_) * D_);
    float x0 = src[l], x1 = src[32 + l];

    float h = sb1[l];
#pragma unroll
    for (int k = 0; k < 32; k++) h = fmaf(__shfl_sync(0xffffffffu, x0, k), sW1[k * 32 + l], h);
#pragma unroll
    for (int k = 0; k < 32; k++) h = fmaf(__shfl_sync(0xffffffffu, x1, k), sW1[(32 + k) * 32 + l], h);
    h = fmaxf(h, 0.f);

    float h2 = sb2[l];
#pragma unroll
    for (int k = 0; k < 32; k++) h2 = fmaf(__shfl_sync(0xffffffffu, h, k), sW2[k * 32 + l], h2);
    h2 = fmaxf(h2, 0.f);

    float h3 = sb3[l];
#pragma unroll
    for (int k = 0; k < 32; k++) h3 = fmaf(__shfl_sync(0xffffffffu, h2, k), sW3[k * 32 + l], h3);
    float v = fmaxf(h3, 0.f);

    float nx = v * v;
#pragma unroll
    for (int o = 16; o > 0; o >>= 1) nx += __shfl_xor_sync(0xffffffffu, nx, o);

    float vs = (row < N_) ? v * LOG2E : v;
    __half hi = __float2half_rn(vs);
    g_Fhi[(size_t)row * H_ + l] = hi;
    g_Flo[(size_t)row * H_ + l] = __float2half_rn(vs - __half2float(hi));
    if (l == 0) g_Fn[row] = -HALF_L2E * nx;
}

// ---------------- kernel 2: HMMA flash kernel (512 thr, 256 rows/CTA) ----------------
__global__ __launch_bounds__(THREADS)
void dist_kernel()
{
    extern __shared__ char smem[];
    u32 sb = smem_u32(smem);
    int tid = threadIdx.x, w = tid >> 5, l = tid & 31;
    int g = l >> 2, tig = l & 3;
    int row0 = blockIdx.x * TTM;
    int m0   = blockIdx.y * (M_ / MSPLIT);

    // ---- preamble: A tile (2 chunks/thread) + tile0 of B/V/cy
    {
#pragma unroll
        for (int q = 0; q < 2; q++) {
            int id = tid + q * THREADS, r = id >> 2, c = id & 3;
            *(uint4*)(smem + S_AHI + r * PITCH + c * 16) = *(const uint4*)(g_Fhi + (size_t)(row0 + r) * H_ + c * 8);
            *(uint4*)(smem + S_ALO + r * PITCH + c * 16) = *(const uint4*)(g_Flo + (size_t)(row0 + r) * H_ + c * 8);
        }
        { int r = tid >> 2, c = tid & 3;
          *(uint4*)(smem + S_B + r * PITCH + c * 16)         = *(const uint4*)(g_Fhi + (size_t)(N_ + m0 + r) * H_ + c * 8);
          *(uint4*)(smem + S_B + 10240 + r * PITCH + c * 16) = *(const uint4*)(g_Flo + (size_t)(N_ + m0 + r) * H_ + c * 8); }
        if (tid < 128)      *(uint4*)(smem + S_V + tid * 16)          = *(const uint4*)(g_Vhi + (size_t)(m0 + tid) * T_);
        else if (tid < 256) *(uint4*)(smem + S_V + 2048 + (tid-128)*16) = *(const uint4*)(g_Vlo + (size_t)(m0 + tid - 128) * T_);
        else if (tid < 384) ((float*)(smem + S_CY))[tid - 256] = g_Fn[N_ + m0 + tid - 256];
    }
    __syncthreads();

    // ---- persistent A fragments
    u32 aH0[4], aH1[4], aL0[4], aL1[4];
    {
        u32 arow = (u32)(w * 16 + (l & 15)) * PITCH + (u32)(l >> 4) * 16;
        ldmx4(aH0[0], aH0[1], aH0[2], aH0[3], sb + S_AHI + arow);
        ldmx4(aH1[0], aH1[1], aH1[2], aH1[3], sb + S_AHI + arow + 32);
        ldmx4(aL0[0], aL0[1], aL0[2], aL0[3], sb + S_ALO + arow);
        ldmx4(aL1[0], aL1[1], aL1[2], aL1[3], sb + S_ALO + arow + 32);
    }

    float cx0 = g_Fn[row0 + w * 16 + g];
    float cx1 = g_Fn[row0 + w * 16 + g + 8];

    float oA0 = 0.f, oA1 = 0.f, oA2 = 0.f, oA3 = 0.f;   // Phi@Vhi chain
    float oB0 = 0.f, oB1 = 0.f, oB2 = 0.f, oB3 = 0.f;   // correction chain
    float s0 = 0.f, s1 = 0.f;

    u32 bArow = (u32)(l & 7) * PITCH + (u32)(l >> 3) * 16;
    u32 vArow = (u32)(l & 15) * 16;

#pragma unroll 1
    for (int i = 0; i < TILES; i++) {
        uint4 nbh, nbl, nv; float ncy = 0.f;
        bool pf = (i + 1 < TILES);
        if (pf) {
            int mb = m0 + (i + 1) * TTN;
            { int r = tid >> 2, c = tid & 3;
              nbh = *(const uint4*)(g_Fhi + (size_t)(N_ + mb + r) * H_ + c * 8);
              nbl = *(const uint4*)(g_Flo + (size_t)(N_ + mb + r) * H_ + c * 8); }
            if (tid < 128)      nv  = *(const uint4*)(g_Vhi + (size_t)(mb + tid) * T_);
            else if (tid < 256) nv  = *(const uint4*)(g_Vlo + (size_t)(mb + tid - 128) * T_);
            else if (tid < 384) ncy = g_Fn[N_ + mb + tid - 256];
        }

        int ib = i & 1;
        u32 Bhi = sb + S_B + ib * 20480, Blo = Bhi + 10240;
        u32 Vhi = sb + S_V + ib * 4096,  Vlo = Vhi + 2048;
        const float* cyb = (const float*)(smem + S_CY + ib * 512);

#pragma unroll 1
        for (int s = 0; s < 8; s++) {
            u32 aP[4], aPl[4];
#pragma unroll
            for (int hhalf = 0; hhalf < 2; hhalf++) {
                int nc = 2 * s + hhalf;
                u32 bh[4], bl[4];
                ldmx4(bh[0], bh[1], bh[2], bh[3], Bhi + (u32)nc * (8 * PITCH) + bArow);
                ldmx4(bl[0], bl[1], bl[2], bl[3], Blo + (u32)nc * (8 * PITCH) + bArow);

                // 3 independent 2-MMA chains
                float cA0 = 0.f, cA1 = 0.f, cA2 = 0.f, cA3 = 0.f;
                float cB0 = 0.f, cB1 = 0.f, cB2 = 0.f, cB3 = 0.f;
                float cC0 = 0.f, cC1 = 0.f, cC2 = 0.f, cC3 = 0.f;
                mma16816(cA0, cA1, cA2, cA3, aH0[0], aH0[1], aH0[2], aH0[3], bh[0], bh[1]);
                mma16816(cB0, cB1, cB2, cB3, aH0[0], aH0[1], aH0[2], aH0[3], bl[0], bl[1]);
                mma16816(cC0, cC1, cC2, cC3, aL0[0], aL0[1], aL0[2], aL0[3], bh[0], bh[1]);
                mma16816(cA0, cA1, cA2, cA3, aH1[0], aH1[1], aH1[2], aH1[3], bh[2], bh[3]);
                mma16816(cB0, cB1, cB2, cB3, aH1[0], aH1[1], aH1[2], aH1[3], bl[2], bl[3]);
                mma16816(cC0, cC1, cC2, cC3, aL1[0], aL1[1], aL1[2], aL1[3], bh[2], bh[3]);
                float c0 = cA0 + cB0 + cC0, c1 = cA1 + cB1 + cC1;
                float c2 = cA2 + cB2 + cC2, c3 = cA3 + cB3 + cC3;

                float2 cy = *(const float2*)(cyb + nc * 8 + 2 * tig);
                float k0 = ex2f(fminf(c0 + (cx0 + cy.x), 0.f));
                float k1 = ex2f(fminf(c1 + (cx0 + cy.y), 0.f));
                float k2 = ex2f(fminf(c2 + (cx1 + cy.x), 0.f));
                float k3 = ex2f(fminf(c3 + (cx1 + cy.y), 0.f));
                s0 += k0 + k1;
                s1 += k2 + k3;

                __half2 h01 = __floats2half2_rn(k0, k1);
                __half2 h23 = __floats2half2_rn(k2, k3);
                float2 f01 = __half22float2(h01);
                float2 f23 = __half22float2(h23);
                __half2 l01 = __floats2half2_rn(k0 - f01.x, k1 - f01.y);
                __half2 l23 = __floats2half2_rn(k2 - f23.x, k3 - f23.y);
                aP [2 * hhalf]     = *(u32*)&h01;
                aP [2 * hhalf + 1] = *(u32*)&h23;
                aPl[2 * hhalf]     = *(u32*)&l01;
                aPl[2 * hhalf + 1] = *(u32*)&l23;
            }

            u32 vh[2], vl[2];
            ldmx2t(vh[0], vh[1], Vhi + (u32)s * 256 + vArow);
            ldmx2t(vl[0], vl[1], Vlo + (u32)s * 256 + vArow);
            mma16816(oA0, oA1, oA2, oA3, aP[0],  aP[1],  aP[2],  aP[3],  vh[0], vh[1]);
            mma16816(oB0, oB1, oB2, oB3, aPl[0], aPl[1], aPl[2], aPl[3], vh[0], vh[1]);
            mma16816(oB0, oB1, oB2, oB3, aP[0],  aP[1],  aP[2],  aP[3],  vl[0], vl[1]);
        }

        if (pf) {
            int ib2 = (i + 1) & 1;
            { int r = tid >> 2, c = tid & 3;
              *(uint4*)(smem + S_B + ib2 * 20480 + r * PITCH + c * 16)         = nbh;
              *(uint4*)(smem + S_B + ib2 * 20480 + 10240 + r * PITCH + c * 16) = nbl; }
            if (tid < 128)      *(uint4*)(smem + S_V + ib2 * 4096 + tid * 16)              = nv;
            else if (tid < 256) *(uint4*)(smem + S_V + ib2 * 4096 + 2048 + (tid-128) * 16) = nv;
            else if (tid < 384) ((float*)(smem + S_CY + ib2 * 512))[tid - 256] = ncy;
        }
        __syncthreads();
    }

    float o0 = oA0 + oB0, o1 = oA1 + oB1, o2 = oA2 + oB2, o3 = oA3 + oB3;

    s0 += __shfl_xor_sync(0xffffffffu, s0, 1);
    s0 += __shfl_xor_sync(0xffffffffu, s0, 2);
    s1 += __shfl_xor_sync(0xffffffffu, s1, 1);
    s1 += __shfl_xor_sync(0xffffffffu, s1, 2);

    int ra = row0 + w * 16 + g;
    float* pa = g_part + ((size_t)ra * MSPLIT + blockIdx.y) * (T_ + 1);
    float* pb = g_part + ((size_t)(ra + 8) * MSPLIT + blockIdx.y) * (T_ + 1);
    pa[2 * tig] = o0; pa[2 * tig + 1] = o1;
    pb[2 * tig] = o2; pb[2 * tig + 1] = o3;
    if (tig == 0) { pa[T_] = s0; pb[T_] = s1; }
}

// ---------------- kernel 3: combine partials, normalize (thread per row*t) ----------------
__global__ __launch_bounds__(256)
void reduce_kernel(float* __restrict__ out)
{
    int idx = blockIdx.x * 256 + threadIdx.x;   // N_*T_
    int row = idx >> 3, t = idx & 7;
    const float* p = g_part + (size_t)row * MSPLIT * (T_ + 1);
    float st = 0.f, sk = 0.f;
#pragma unroll
    for (int c = 0; c < MSPLIT; c++) {
        st += p[c * (T_ + 1) + t];
        sk += p[c * (T_ + 1) + T_];
    }
    out[idx] = st / sk;
}

// ---------------- launch ----------------
extern "C" void kernel_launch(void* const* d_in, const int* in_sizes, int n_in,
                              void* d_out, int out_size)
{
    (void)in_sizes; (void)n_in; (void)out_size;
    const float* X  = (const float*)d_in[0];
    const float* Y  = (const float*)d_in[1];
    const float* Yt = (const float*)d_in[2];
    const float* W1 = (const float*)d_in[3];
    const float* b1 = (const float*)d_in[4];
    const float* W2 = (const float*)d_in[5];
    const float* b2 = (const float*)d_in[6];
    const float* W3 = (const float*)d_in[7];
    const float* b3 = (const float*)d_in[8];
    float* out = (float*)d_out;

    cudaFuncSetAttribute(dist_kernel, cudaFuncAttributeMaxDynamicSharedMemorySize, SMEM_TOTAL);

    mlp_kernel<<<(N_ + M_) / 8 + (M_ * T_) / 256, 256>>>(X, Y, Yt, W1, b1, W2, b2, W3, b3);
    dist_kernel<<<dim3(N_ / TTM, MSPLIT), THREADS, SMEM_TOTAL>>>();
    reduce_kernel<<<(N_ * T_) / 256, 256>>>(out);
}